// round 14
// baseline (speedup 1.0000x reference)
#include <cuda_runtime.h>

#define FULL 0xffffffffu
typedef unsigned int u32;

constexpr int L = 16;
constexpr int RING = 8;
constexpr float LOG2E = 1.4426950408889634f;
constexpr float LN2   = 0.6931471805599453f;

__device__ __forceinline__ float ex2f(float v) {
    float r; asm("ex2.approx.f32 %0,%1;" : "=f"(r) : "f"(v)); return r;
}
__device__ __forceinline__ u32 pkbf(float hi, float lo) {
    u32 r; asm("cvt.rn.bf16x2.f32 %0,%1,%2;" : "=r"(r) : "f"(hi), "f"(lo)); return r;
}
__device__ __forceinline__ u32 mulbf2(u32 a, u32 b) {
    u32 r; asm("mul.rn.bf16x2 %0,%1,%2;" : "=r"(r) : "r"(a), "r"(b)); return r;
}
__device__ __forceinline__ float bflo(u32 v) { return __uint_as_float(v << 16); }
__device__ __forceinline__ float bfhi(u32 v) { return __uint_as_float(v & 0xffff0000u); }

__device__ __forceinline__ void mma16816(
    float& d0, float& d1, float& d2, float& d3,
    u32 a0, u32 a1, u32 a2, u32 a3, u32 b0, u32 b1)
{
    asm volatile(
        "mma.sync.aligned.m16n8k16.row.col.f32.bf16.bf16.f32 "
        "{%0,%1,%2,%3}, {%4,%5,%6,%7}, {%8,%9}, {%10,%11,%12,%13};"
        : "=f"(d0), "=f"(d1), "=f"(d2), "=f"(d3)
        : "r"(a0), "r"(a1), "r"(a2), "r"(a3), "r"(b0), "r"(b1),
          "f"(0.f), "f"(0.f), "f"(0.f), "f"(0.f));
}

// state permutation on the MMA k/n axes
__host__ __device__ __forceinline__ int sigma(int i) {
    return (i < 8) ? ((i & 1) ? 2 * i - 1 : 2 * i)
                   : ((i & 1) ? 2 * i - 15 : 2 * i - 14);
}

// Grid = 128 blocks x 32 batches. Block = 640 threads = 20 warps:
//  w0-7  : fwd recursion, batch groups 0-7 (4 batches each)
//  w8-15 : bwd recursion, groups 0-7
//  w16-19: emit + transition scores (8 batches each)
// SMSP k hosts 4 independent recursion chains (fwd k, fwd k+4, bwd k, bwd k+4)
// + 1 early-finishing emit warp.
// Per warp: 4 batches in MMA rows 0-3 (lanes g>=4 duplicate batch 3 - free,
// instruction count is per-warp not per-lane); rows 8-15 duplicate via A1=A0.
__global__ __launch_bounds__(640, 1) void crf_kernel(
    const float* __restrict__ x, const float* __restrict__ trans,
    const int* __restrict__ label, const int* __restrict__ length,
    float* __restrict__ out, int B, int T)
{
    __shared__ float sE[L * L];
    __shared__ float sT[L * L];
    __shared__ u32   sFA[8][32][2];   // fwd final (A0, A2) per lane
    __shared__ int   sMf[8][4];
    __shared__ float sScore[32];

    int tid  = threadIdx.x;
    int lane = tid & 31;
    int w    = tid >> 5;
    int g    = lane >> 2;     // MMA row 0..7 (rows 4-7 duplicate batch 3)
    int tig  = lane & 3;

    if (tid < L * L) {
        float tv = trans[tid];
        sT[tid] = tv;
        sE[tid] = tv * LOG2E;
    }
    __syncthreads();

    int blockBase = blockIdx.x * 32;

    if (w < 16) {
        bool isBwd = w >= 8;
        int grp = w & 7;
        int rb = min(g, 3);                    // real batch row
        int b = blockBase + grp * 4 + rb;
        int len = length[b];
        int m = (len - 1) >> 1;
        int cnt  = isBwd ? max(len - 2 - m, 0) : m;
        int base = isBwd ? (len - 2) : 1;
        int dir  = isBwd ? -1 : 1;
        int cl   = max(cnt - 1, 0);

        int kMax = cnt;
#pragma unroll
        for (int o = 4; o <= 16; o <<= 1)
            kMax = max(kMax, __shfl_xor_sync(FULL, kMax, o));
        int kMaxPad = (kMax + RING - 1) & ~(RING - 1);

        // B fragments with sigma on both axes:
        u32 b00, b01, b10, b11;
        {
            int r0 = 4 * tig;
            int cA = sigma(g);
            int cB = sigma(g + 8);
            float e00, e01, e02, e03, e10, e11, e12, e13;
            if (!isBwd) {
                e00 = sE[r0 * L + cA];       e01 = sE[(r0 + 1) * L + cA];
                e02 = sE[(r0 + 2) * L + cA]; e03 = sE[(r0 + 3) * L + cA];
                e10 = sE[r0 * L + cB];       e11 = sE[(r0 + 1) * L + cB];
                e12 = sE[(r0 + 2) * L + cB]; e13 = sE[(r0 + 3) * L + cB];
            } else {
                e00 = sE[cA * L + r0];       e01 = sE[cA * L + r0 + 1];
                e02 = sE[cA * L + r0 + 2];   e03 = sE[cA * L + r0 + 3];
                e10 = sE[cB * L + r0];       e11 = sE[cB * L + r0 + 1];
                e12 = sE[cB * L + r0 + 2];   e13 = sE[cB * L + r0 + 3];
            }
            b00 = pkbf(ex2f(e01), ex2f(e00));
            b01 = pkbf(ex2f(e03), ex2f(e02));
            b10 = pkbf(ex2f(e11), ex2f(e10));
            b11 = pkbf(ex2f(e13), ex2f(e12));
        }

        // thread tig owns states 4*tig..4*tig+3 of batch b (one float4 per row)
        const float* p = x + (size_t)b * T * L + tig * 4;

        // init: s = exp(x at row 0 (fwd) / len-1 (bwd))
        int ir = isBwd ? (len - 1) : 0;
        float4 iv = *(const float4*)(p + (size_t)ir * L);
        u32 A0 = pkbf(ex2f(iv.y * LOG2E), ex2f(iv.x * LOG2E));
        u32 A2 = pkbf(ex2f(iv.w * LOG2E), ex2f(iv.z * LOG2E));
        int Ms = 0;

        // RING-deep prefetch ring of x rows (clamped)
        float4 r[RING];
#pragma unroll
        for (int d = 0; d < RING; ++d) {
            int row = max(base + dir * min(d, cl), 0);
            r[d] = *(const float4*)(p + (size_t)row * L);
        }

        for (int k0 = 0; k0 < kMaxPad; k0 += RING) {
#pragma unroll
            for (int kk = 0; kk < RING; ++kk) {
                int k = k0 + kk;

                float d0, d1, d2, d3, f0, f1, f2, f3;
                mma16816(d0, d1, d2, d3, A0, A0, A2, A2, b00, b01);
                mma16816(f0, f1, f2, f3, A0, A0, A2, A2, b10, b11);

                float4 xv = r[kk];
                float e0 = ex2f(xv.x * LOG2E), e1 = ex2f(xv.y * LOG2E);
                float e2 = ex2f(xv.z * LOG2E), e3 = ex2f(xv.w * LOG2E);

                // refill ring slot with row k+RING
                {
                    int row = max(base + dir * min(k + RING, cl), 0);
                    r[kk] = *(const float4*)(p + (size_t)row * L);
                }

                u32 n0 = pkbf(d1 * e1, d0 * e0);
                u32 n2 = pkbf(f1 * e3, f0 * e2);

                bool act = k < cnt;
                A0 = act ? n0 : A0;
                A2 = act ? n2 : A2;

                if (kk == RING - 1) {   // exponent-only rescale (every 8 steps)
                    u32 s0 = __shfl_sync(FULL, A0, lane & ~3);
                    int ee = (int)((s0 >> 7) & 0xff) - 127;
                    u32 h = (u32)(127 - ee) << 7;
                    u32 sc = act ? (h | (h << 16)) : 0x3f803f80u;
                    Ms += act ? ee : 0;
                    A0 = mulbf2(A0, sc);
                    A2 = mulbf2(A2, sc);
                }
            }
        }

        if (!isBwd) {
            sFA[grp][lane][0] = A0;
            sFA[grp][lane][1] = A2;
            if (tig == 0 && g < 4) sMf[grp][g] = Ms;
            __syncthreads();
        } else {
            // beta_m = E * q~ : one more (plain) double-MMA
            float d0, d1, d2, d3, f0, f1, f2, f3;
            mma16816(d0, d1, d2, d3, A0, A0, A2, A2, b00, b01);
            mma16816(f0, f1, f2, f3, A0, A0, A2, A2, b10, b11);
            if (len == 1) { d0 = d1 = 1.f; f0 = f1 = 1.f; }

            __syncthreads();

            u32 a0 = sFA[grp][lane][0], a2 = sFA[grp][lane][1];
            float pr = d0 * bflo(a0) + d1 * bfhi(a0)
                     + f0 * bflo(a2) + f1 * bfhi(a2);
            pr += __shfl_xor_sync(FULL, pr, 1);
            pr += __shfl_xor_sync(FULL, pr, 2);
            float z = __logf(pr) + (float)(Ms + sMf[grp][rb]) * LN2;
            if (tig == 0 && g < 4) out[b] = z - sScore[grp * 4 + g];
        }
    } else {
        // ---------------- emit / transition warps ----------------
        int we = w - 16;
#pragma unroll 1
        for (int k2 = 0; k2 < 8; ++k2) {
            int sl = we * 8 + k2;
            int bb = blockBase + sl;
            const int*   lb = label + (size_t)bb * T;
            const float* xb = x + (size_t)bb * T * L;
            int ll = length[bb];

            float acc = 0.f;
            for (int t = lane; t < ll; t += 32) {
                int lab = lb[t];
                acc += __ldg(xb + t * L + lab);
                if (t >= 1) acc += sT[lb[t - 1] * L + lab];
            }
            acc += __shfl_xor_sync(FULL, acc, 16);
            acc += __shfl_xor_sync(FULL, acc, 8);
            acc += __shfl_xor_sync(FULL, acc, 4);
            acc += __shfl_xor_sync(FULL, acc, 2);
            acc += __shfl_xor_sync(FULL, acc, 1);
            if (lane == 0) sScore[sl] = acc;
        }
        __syncthreads();
    }
}

extern "C" void kernel_launch(void* const* d_in, const int* in_sizes, int n_in,
                              void* d_out, int out_size) {
    const float* x      = (const float*)d_in[0];
    const float* trans  = (const float*)d_in[1];
    const int*   label  = (const int*)d_in[2];
    const int*   length = (const int*)d_in[3];
    float*       out    = (float*)d_out;

    int B = in_sizes[3];                 // 4096
    int T = in_sizes[2] / B;             // 512

    int grid = (B + 31) / 32;            // 32 batches per block, 128 blocks
    crf_kernel<<<grid, 640>>>(x, trans, label, length, out, B, T);
}